// round 2
// baseline (speedup 1.0000x reference)
#include <cuda_runtime.h>
#include <cuda_fp16.h>
#include <cstdint>

// ============================================================================
// LocationAwareAttention  B=32, S=2048, D=512   (family-common PTX only:
// mma.sync.m16n8k16.f16 + ldmatrix + cp.async — NO tcgen05, target is sm_103)
//
//   loc   = conv1d(last_energy, k=3, pad=1) + conv_b
//   hid   = tanh(q@w_q + v@w_v + loc + bias)
//   score = hid @ score_w + score_b ; align = softmax(score)
//   ctx   = align^T v
// Output: d_out = [ctx (B*D) | align (B*S)] fp32
// ============================================================================

#define BB 32
#define SS 2048
#define DD 512

__device__ __half g_wvt[DD * DD];     // w_v^T [n][k] fp16
__device__ float  g_qw[BB * DD];      // q@w_q + bias + conv_b
__device__ float  g_scores[BB * SS];

// ---------------- SMEM layout (bytes) ----------------
#define SM_B0   0                      // B tile buf0: 512n x 64k fp16 = 64KB
#define SM_B1   65536
#define SM_AH0  131072                 // A hi buf0: 64 x 64 fp16 = 8KB
#define SM_AL0  139264
#define SM_AH1  147456
#define SM_AL1  155648
#define SM_QWB  163840                 // 512 f32
#define SM_CW0  (SM_QWB + 2048)
#define SM_CW1  (SM_CW0 + 2048)
#define SM_CW2  (SM_CW1 + 2048)
#define SM_SW   (SM_CW2 + 2048)
#define SM_E0   (SM_SW + 2048)         // 64 f32
#define SM_E1   (SM_E0 + 256)
#define SM_E2   (SM_E1 + 256)
#define SM_RED  (SM_E2 + 256)          // 64 x 8 f32
#define SM_TOT  (SM_RED + 2048)        // 176896 B

// ---------------- PTX helpers (sm_80-baseline instructions) ----------------
__device__ __forceinline__ uint32_t s2u(const void* p) {
    uint32_t a;
    asm("{ .reg .u64 t; cvta.to.shared.u64 t, %1; cvt.u32.u64 %0, t; }"
        : "=r"(a) : "l"(p));
    return a;
}
__device__ __forceinline__ void cp16(uint32_t dst, const void* src) {
    asm volatile("cp.async.ca.shared.global [%0], [%1], 16;"
                 :: "r"(dst), "l"(src) : "memory");
}
__device__ __forceinline__ void cp_commit() {
    asm volatile("cp.async.commit_group;" ::: "memory");
}
__device__ __forceinline__ void cp_wait0() {
    asm volatile("cp.async.wait_group 0;" ::: "memory");
}
__device__ __forceinline__ void ldsm4(uint32_t& r0, uint32_t& r1,
                                      uint32_t& r2, uint32_t& r3, uint32_t a) {
    asm volatile("ldmatrix.sync.aligned.m8n8.x4.shared.b16 {%0,%1,%2,%3}, [%4];"
                 : "=r"(r0), "=r"(r1), "=r"(r2), "=r"(r3) : "r"(a));
}
__device__ __forceinline__ void mma16816(float* d, const uint32_t* a,
                                         const uint32_t* b) {
    asm volatile(
        "mma.sync.aligned.m16n8k16.row.col.f32.f16.f16.f32 "
        "{%0,%1,%2,%3}, {%4,%5,%6,%7}, {%8,%9}, {%0,%1,%2,%3};"
        : "+f"(d[0]), "+f"(d[1]), "+f"(d[2]), "+f"(d[3])
        : "r"(a[0]), "r"(a[1]), "r"(a[2]), "r"(a[3]), "r"(b[0]), "r"(b[1]));
}
__device__ __forceinline__ uint32_t packh(__half a, __half b) {
    __half2 h2; h2.x = a; h2.y = b;
    return *(uint32_t*)&h2;
}
// swizzled in-tile byte offset: rows of 128B, 16B-chunk rotation by (row&7)
__device__ __forceinline__ uint32_t swz(uint32_t row, uint32_t colByte) {
    return row * 128u + (colByte ^ ((row & 7u) << 4));
}

// ============================================================================
// prep: w_v^T -> fp16  [n][k]
// ============================================================================
__global__ void prep_wv_kernel(const float* __restrict__ w_v) {
    int n = blockIdx.x;
    for (int k = threadIdx.x; k < DD; k += blockDim.x)
        g_wvt[n * DD + k] = __float2half_rn(w_v[k * DD + n]);
}

// ============================================================================
// prep: g_qw[b,d] = q[b]@w_q[:,d] + bias[d] + conv_b[d]
// ============================================================================
__global__ void prep_qw_kernel(const float* __restrict__ query,
                               const float* __restrict__ w_q,
                               const float* __restrict__ bias,
                               const float* __restrict__ conv_b) {
    __shared__ float qs[DD];
    int b = blockIdx.x, d = threadIdx.x;
    qs[d] = query[b * DD + d];
    __syncthreads();
    float acc = bias[d] + conv_b[d];
#pragma unroll 4
    for (int k = 0; k < DD; ++k)
        acc = fmaf(qs[k], w_q[k * DD + d], acc);
    g_qw[b * DD + d] = acc;
}

// ============================================================================
// scores: per block M=64 rows x N=512 (full D), K=512.
// hidden = value @ w_v with A split fp16 hi/lo (2 mma passes, shared B),
// fused epilogue -> g_scores.
// Grid: 1024 blocks (b*32 + tile), 256 threads (8 warps, warp tile 64x64).
// ============================================================================
__global__ void __launch_bounds__(256, 1)
scores_kernel(const float* __restrict__ value,
              const float* __restrict__ energy,
              const float* __restrict__ conv_w,
              const float* __restrict__ score_w,
              const float* __restrict__ score_b) {
    extern __shared__ char smem[];
    const uint32_t sb = s2u(smem);
    const int tid = threadIdx.x, wid = tid >> 5, lid = tid & 31;
    const int b = blockIdx.x >> 5, tile = blockIdx.x & 31;
    const int s0 = tile * 64;
    const size_t grow0 = (size_t)b * SS + s0;

    // ---- epilogue constants ----
    float* c_qwb = (float*)(smem + SM_QWB);
    float* c_cw0 = (float*)(smem + SM_CW0);
    float* c_cw1 = (float*)(smem + SM_CW1);
    float* c_cw2 = (float*)(smem + SM_CW2);
    float* c_sw  = (float*)(smem + SM_SW);
    for (int d = tid; d < DD; d += 256) {
        c_qwb[d] = g_qw[b * DD + d];
        c_cw0[d] = conv_w[d * 3 + 0];
        c_cw1[d] = conv_w[d * 3 + 1];
        c_cw2[d] = conv_w[d * 3 + 2];
        c_sw[d]  = score_w[d];
    }
    if (tid < 64) {
        int s = s0 + tid, gs = b * SS + s;
        ((float*)(smem + SM_E1))[tid] = energy[gs];
        ((float*)(smem + SM_E0))[tid] = (s > 0)      ? energy[gs - 1] : 0.f;
        ((float*)(smem + SM_E2))[tid] = (s < SS - 1) ? energy[gs + 1] : 0.f;
    }

    float4 pre[4];  // prefetched A fp32 (2 tasks x 8 floats)

    // A gmem->regs (value fp32), tasks: 512 = 64 rows x 8 chunks of 8 floats
    auto ldA = [&](int ch) {
        int kb = ch * 64;
#pragma unroll
        for (int q = 0; q < 2; ++q) {
            int t = tid * 2 + q, r = t >> 3, c = t & 7;
            const float4* src =
                (const float4*)(value + (grow0 + r) * DD + kb + c * 8);
            pre[q * 2]     = src[0];
            pre[q * 2 + 1] = src[1];
        }
    };
    // regs -> SMEM fp16 hi/lo (swizzled)
    auto stsA = [&](int ch) {
        char* ah = smem + ((ch & 1) ? SM_AH1 : SM_AH0);
        char* al = smem + ((ch & 1) ? SM_AL1 : SM_AL0);
#pragma unroll
        for (int q = 0; q < 2; ++q) {
            int t = tid * 2 + q, r = t >> 3, c = t & 7;
            uint32_t off = swz((uint32_t)r, (uint32_t)c * 16);
            uint32_t hh[4], ll[4];
#pragma unroll
            for (int j = 0; j < 2; ++j) {
                float4 v = pre[q * 2 + j];
                __half hx = __float2half_rn(v.x), hy = __float2half_rn(v.y);
                __half hz = __float2half_rn(v.z), hw = __float2half_rn(v.w);
                __half lx = __float2half_rn(v.x - __half2float(hx));
                __half ly = __float2half_rn(v.y - __half2float(hy));
                __half lz = __float2half_rn(v.z - __half2float(hz));
                __half lw = __float2half_rn(v.w - __half2float(hw));
                hh[j * 2]     = packh(hx, hy);
                hh[j * 2 + 1] = packh(hz, hw);
                ll[j * 2]     = packh(lx, ly);
                ll[j * 2 + 1] = packh(lz, lw);
            }
            *(uint4*)(ah + off) = make_uint4(hh[0], hh[1], hh[2], hh[3]);
            *(uint4*)(al + off) = make_uint4(ll[0], ll[1], ll[2], ll[3]);
        }
    };
    // B tile via cp.async: 512n x 64k fp16 = 4096 x 16B
    auto cpB = [&](int ch) {
        int kb = ch * 64;
        uint32_t bbuf = sb + ((ch & 1) ? SM_B1 : SM_B0);
#pragma unroll
        for (int q = 0; q < 16; ++q) {
            int t = tid + q * 256, n = t >> 3, c = t & 7;
            cp16(bbuf + swz((uint32_t)n, (uint32_t)c * 16),
                 g_wvt + n * DD + kb + c * 8);
        }
        cp_commit();
    };

    float acc[4][8][4];
#pragma unroll
    for (int i = 0; i < 4; ++i)
#pragma unroll
        for (int j = 0; j < 8; ++j)
#pragma unroll
            for (int c = 0; c < 4; ++c) acc[i][j][c] = 0.f;

    const int nwb = wid * 64;

    auto compute = [&](int ch) {
        uint32_t abh = sb + ((ch & 1) ? SM_AH1 : SM_AH0);
        uint32_t abl = sb + ((ch & 1) ? SM_AL1 : SM_AL0);
        uint32_t bb  = sb + ((ch & 1) ? SM_B1 : SM_B0);
#pragma unroll
        for (int s = 0; s < 4; ++s) {
            uint32_t bfr[8][2];
#pragma unroll
            for (int np = 0; np < 4; ++np) {
                uint32_t row = nwb + np * 16 + ((lid & 16) >> 1) + (lid & 7);
                uint32_t col = s * 32 + ((lid & 8) << 1);
                ldsm4(bfr[np * 2][0], bfr[np * 2][1],
                      bfr[np * 2 + 1][0], bfr[np * 2 + 1][1],
                      bb + swz(row, col));
            }
#pragma unroll
            for (int mi = 0; mi < 4; ++mi) {
                uint32_t row = mi * 16 + (lid & 15);
                uint32_t col = s * 32 + (lid & 16);
                uint32_t axr = swz(row, col);
                uint32_t ah[4], al[4];
                ldsm4(ah[0], ah[1], ah[2], ah[3], abh + axr);
                ldsm4(al[0], al[1], al[2], al[3], abl + axr);
#pragma unroll
                for (int ni = 0; ni < 8; ++ni) {
                    mma16816(acc[mi][ni], ah, bfr[ni]);
                    mma16816(acc[mi][ni], al, bfr[ni]);
                }
            }
        }
    };

    // ---- pipelined K loop (8 chunks of 64) ----
    ldA(0);
    cpB(0);
    stsA(0);
    for (int ch = 0; ch < 8; ++ch) {
        cp_wait0();           // B(ch) arrived (only outstanding group)
        __syncthreads();      // A(ch) STS + B(ch) visible; prev compute done
        if (ch < 7) { ldA(ch + 1); cpB(ch + 1); }
        compute(ch);
        if (ch < 7) stsA(ch + 1);
    }

    // ---- epilogue: x = acc + qw + conv(e); score += tanh(x)*sw ----
    const float* E0 = (const float*)(smem + SM_E0);
    const float* E1 = (const float*)(smem + SM_E1);
    const float* E2 = (const float*)(smem + SM_E2);
    float e0r[8], e1r[8], e2r[8];
#pragma unroll
    for (int mi = 0; mi < 4; ++mi)
#pragma unroll
        for (int h = 0; h < 2; ++h) {
            int r = mi * 16 + h * 8 + (lid >> 2);
            e0r[mi * 2 + h] = E0[r];
            e1r[mi * 2 + h] = E1[r];
            e2r[mi * 2 + h] = E2[r];
        }
    float part[8];
#pragma unroll
    for (int i = 0; i < 8; ++i) part[i] = 0.f;

#pragma unroll
    for (int ni = 0; ni < 8; ++ni) {
        int d0 = nwb + ni * 8 + 2 * (lid & 3);
        float qb0 = c_qwb[d0], qb1 = c_qwb[d0 + 1];
        float w00 = c_cw0[d0], w01 = c_cw0[d0 + 1];
        float w10 = c_cw1[d0], w11 = c_cw1[d0 + 1];
        float w20 = c_cw2[d0], w21 = c_cw2[d0 + 1];
        float sw0 = c_sw[d0],  sw1 = c_sw[d0 + 1];
#pragma unroll
        for (int mi = 0; mi < 4; ++mi)
#pragma unroll
            for (int h = 0; h < 2; ++h) {
                int pi = mi * 2 + h;
                float x0 = acc[mi][ni][h * 2] + qb0
                         + e0r[pi] * w00 + e1r[pi] * w10 + e2r[pi] * w20;
                float x1 = acc[mi][ni][h * 2 + 1] + qb1
                         + e0r[pi] * w01 + e1r[pi] * w11 + e2r[pi] * w21;
                float t0 = 1.f - __fdividef(2.f, __expf(2.f * x0) + 1.f);
                float t1 = 1.f - __fdividef(2.f, __expf(2.f * x1) + 1.f);
                part[pi] = fmaf(t0, sw0, fmaf(t1, sw1, part[pi]));
            }
    }
#pragma unroll
    for (int pi = 0; pi < 8; ++pi) {
        part[pi] += __shfl_xor_sync(0xffffffffu, part[pi], 1);
        part[pi] += __shfl_xor_sync(0xffffffffu, part[pi], 2);
    }
    float* red = (float*)(smem + SM_RED);
    if ((lid & 3) == 0) {
#pragma unroll
        for (int mi = 0; mi < 4; ++mi)
#pragma unroll
            for (int h = 0; h < 2; ++h) {
                int r = mi * 16 + h * 8 + (lid >> 2);
                red[r * 8 + wid] = part[mi * 2 + h];
            }
    }
    __syncthreads();
    if (tid < 64) {
        float sum = score_b[0];
#pragma unroll
        for (int w = 0; w < 8; ++w) sum += red[tid * 8 + w];
        g_scores[b * SS + s0 + tid] = sum;
    }
}

// ============================================================================
// softmax per batch -> align
// ============================================================================
__global__ void softmax_kernel(float* __restrict__ align_out) {
    __shared__ float red[1024];
    int b = blockIdx.x, t = threadIdx.x;
    const float* s = g_scores + b * SS;
    float a = s[t], c = s[t + 1024];
    red[t] = fmaxf(a, c);
    __syncthreads();
    for (int o = 512; o > 0; o >>= 1) {
        if (t < o) red[t] = fmaxf(red[t], red[t + o]);
        __syncthreads();
    }
    float mx = red[0];
    __syncthreads();
    float ea = __expf(a - mx), ec = __expf(c - mx);
    red[t] = ea + ec;
    __syncthreads();
    for (int o = 512; o > 0; o >>= 1) {
        if (t < o) red[t] += red[t + o];
        __syncthreads();
    }
    float inv = 1.f / red[0];
    align_out[b * SS + t] = ea * inv;
    align_out[b * SS + t + 1024] = ec * inv;
}

// ============================================================================
// context: ctx[b,d] = sum_s align[b,s] * value[b,s,d]
// ============================================================================
__global__ void zero_ctx_kernel(float* __restrict__ ctx) {
    int i = blockIdx.x * blockDim.x + threadIdx.x;
    if (i < BB * DD) ctx[i] = 0.f;
}
__global__ void context_kernel(const float* __restrict__ value,
                               const float* __restrict__ align,
                               float* __restrict__ ctx) {
    int b = blockIdx.x, dch = blockIdx.y, sch = blockIdx.z;
    int d = dch * 128 + threadIdx.x;
    const float* vb = value + ((size_t)b * SS + sch * 256) * DD + d;
    const float* ab = align + b * SS + sch * 256;
    float acc = 0.f;
#pragma unroll 8
    for (int s = 0; s < 256; ++s)
        acc = fmaf(ab[s], vb[(size_t)s * DD], acc);
    atomicAdd(&ctx[b * DD + d], acc);
}

// ============================================================================
// launch
// ============================================================================
extern "C" void kernel_launch(void* const* d_in, const int* in_sizes, int n_in,
                              void* d_out, int out_size) {
    const float* query   = (const float*)d_in[0];
    const float* value   = (const float*)d_in[1];
    const float* energy  = (const float*)d_in[2];
    const float* conv_w  = (const float*)d_in[3];
    const float* conv_b  = (const float*)d_in[4];
    const float* w_q     = (const float*)d_in[5];
    const float* w_v     = (const float*)d_in[6];
    const float* bias    = (const float*)d_in[7];
    const float* score_w = (const float*)d_in[8];
    const float* score_b = (const float*)d_in[9];
    float* out_ctx   = (float*)d_out;            // [B*D]
    float* out_align = (float*)d_out + BB * DD;  // [B*S]

    static bool attr_set = false;
    cudaFuncSetAttribute(scores_kernel,
                         cudaFuncAttributeMaxDynamicSharedMemorySize, SM_TOT);
    (void)attr_set;

    prep_wv_kernel<<<DD, 256>>>(w_v);
    prep_qw_kernel<<<BB, DD>>>(query, w_q, bias, conv_b);
    scores_kernel<<<BB * (SS / 64), 256, SM_TOT>>>(value, energy, conv_w,
                                                   score_w, score_b);
    softmax_kernel<<<BB, 1024>>>(out_align);
    zero_ctx_kernel<<<(BB * DD + 255) / 256, 256>>>(out_ctx);
    context_kernel<<<dim3(BB, DD / 128, SS / 256), 128>>>(value, out_align,
                                                          out_ctx);
}

// round 3
// speedup vs baseline: 1.2806x; 1.2806x over previous
#include <cuda_runtime.h>
#include <cuda_fp16.h>
#include <cstdint>

// ============================================================================
// LocationAwareAttention  B=32, S=2048, D=512   (family-common PTX only:
// mma.sync.m16n8k16.f16 + ldmatrix + cp.async — NO tcgen05, target is sm_103)
//
// R3: single fp16 pass for A (was hi/lo split). Measured R2 error budget
// (1.65e-4 from B rounding alone) says A rounding adds ~sqrt(2)x -> ~2.3e-4,
// well under 1e-3. Halves the HMMA count, which R2 showed is the binding
// constraint (legacy mma.sync rt ~16cyc/SMSP).
// Output: d_out = [ctx (B*D) | align (B*S)] fp32
// ============================================================================

#define BB 32
#define SS 2048
#define DD 512

__device__ __half g_wvt[DD * DD];     // w_v^T [n][k] fp16
__device__ float  g_qw[BB * DD];      // q@w_q + bias + conv_b
__device__ float  g_scores[BB * SS];

// ---------------- SMEM layout (bytes) ----------------
#define SM_B0   0                      // B tile buf0: 512n x 64k fp16 = 64KB
#define SM_B1   65536
#define SM_AH0  131072                 // A buf0: 64 x 64 fp16 = 8KB
#define SM_AH1  139264
#define SM_QWB  147456                 // 512 f32
#define SM_CW0  (SM_QWB + 2048)
#define SM_CW1  (SM_CW0 + 2048)
#define SM_CW2  (SM_CW1 + 2048)
#define SM_SW   (SM_CW2 + 2048)
#define SM_E0   (SM_SW + 2048)         // 64 f32
#define SM_E1   (SM_E0 + 256)
#define SM_E2   (SM_E1 + 256)
#define SM_RED  (SM_E2 + 256)          // 64 x 8 f32
#define SM_TOT  (SM_RED + 2048)        // 160512 B

// ---------------- PTX helpers (sm_80-baseline instructions) ----------------
__device__ __forceinline__ uint32_t s2u(const void* p) {
    uint32_t a;
    asm("{ .reg .u64 t; cvta.to.shared.u64 t, %1; cvt.u32.u64 %0, t; }"
        : "=r"(a) : "l"(p));
    return a;
}
__device__ __forceinline__ void cp16(uint32_t dst, const void* src) {
    asm volatile("cp.async.ca.shared.global [%0], [%1], 16;"
                 :: "r"(dst), "l"(src) : "memory");
}
__device__ __forceinline__ void cp_commit() {
    asm volatile("cp.async.commit_group;" ::: "memory");
}
__device__ __forceinline__ void cp_wait0() {
    asm volatile("cp.async.wait_group 0;" ::: "memory");
}
__device__ __forceinline__ void ldsm4(uint32_t& r0, uint32_t& r1,
                                      uint32_t& r2, uint32_t& r3, uint32_t a) {
    asm volatile("ldmatrix.sync.aligned.m8n8.x4.shared.b16 {%0,%1,%2,%3}, [%4];"
                 : "=r"(r0), "=r"(r1), "=r"(r2), "=r"(r3) : "r"(a));
}
__device__ __forceinline__ void mma16816(float* d, const uint32_t* a,
                                         const uint32_t* b) {
    asm volatile(
        "mma.sync.aligned.m16n8k16.row.col.f32.f16.f16.f32 "
        "{%0,%1,%2,%3}, {%4,%5,%6,%7}, {%8,%9}, {%0,%1,%2,%3};"
        : "+f"(d[0]), "+f"(d[1]), "+f"(d[2]), "+f"(d[3])
        : "r"(a[0]), "r"(a[1]), "r"(a[2]), "r"(a[3]), "r"(b[0]), "r"(b[1]));
}
__device__ __forceinline__ uint32_t packh(__half a, __half b) {
    __half2 h2; h2.x = a; h2.y = b;
    return *(uint32_t*)&h2;
}
// swizzled in-tile byte offset: rows of 128B, 16B-chunk rotation by (row&7)
__device__ __forceinline__ uint32_t swz(uint32_t row, uint32_t colByte) {
    return row * 128u + (colByte ^ ((row & 7u) << 4));
}

// ============================================================================
// prep: w_v^T -> fp16  [n][k]
// ============================================================================
__global__ void prep_wv_kernel(const float* __restrict__ w_v) {
    int n = blockIdx.x;
    for (int k = threadIdx.x; k < DD; k += blockDim.x)
        g_wvt[n * DD + k] = __float2half_rn(w_v[k * DD + n]);
}

// ============================================================================
// prep: g_qw[b,d] = q[b]@w_q[:,d] + bias[d] + conv_b[d]
// ============================================================================
__global__ void prep_qw_kernel(const float* __restrict__ query,
                               const float* __restrict__ w_q,
                               const float* __restrict__ bias,
                               const float* __restrict__ conv_b) {
    __shared__ float qs[DD];
    int b = blockIdx.x, d = threadIdx.x;
    qs[d] = query[b * DD + d];
    __syncthreads();
    float acc = bias[d] + conv_b[d];
#pragma unroll 4
    for (int k = 0; k < DD; ++k)
        acc = fmaf(qs[k], w_q[k * DD + d], acc);
    g_qw[b * DD + d] = acc;
}

// ============================================================================
// scores: per block M=64 rows x N=512 (full D), K=512, single fp16 pass.
// Grid: 1024 blocks (b*32 + tile), 256 threads (8 warps, warp tile 64x64).
// ============================================================================
__global__ void __launch_bounds__(256, 1)
scores_kernel(const float* __restrict__ value,
              const float* __restrict__ energy,
              const float* __restrict__ conv_w,
              const float* __restrict__ score_w,
              const float* __restrict__ score_b) {
    extern __shared__ char smem[];
    const uint32_t sb = s2u(smem);
    const int tid = threadIdx.x, wid = tid >> 5, lid = tid & 31;
    const int b = blockIdx.x >> 5, tile = blockIdx.x & 31;
    const int s0 = tile * 64;
    const size_t grow0 = (size_t)b * SS + s0;

    // ---- epilogue constants ----
    float* c_qwb = (float*)(smem + SM_QWB);
    float* c_cw0 = (float*)(smem + SM_CW0);
    float* c_cw1 = (float*)(smem + SM_CW1);
    float* c_cw2 = (float*)(smem + SM_CW2);
    float* c_sw  = (float*)(smem + SM_SW);
    for (int d = tid; d < DD; d += 256) {
        c_qwb[d] = g_qw[b * DD + d];
        c_cw0[d] = conv_w[d * 3 + 0];
        c_cw1[d] = conv_w[d * 3 + 1];
        c_cw2[d] = conv_w[d * 3 + 2];
        c_sw[d]  = score_w[d];
    }
    if (tid < 64) {
        int s = s0 + tid, gs = b * SS + s;
        ((float*)(smem + SM_E1))[tid] = energy[gs];
        ((float*)(smem + SM_E0))[tid] = (s > 0)      ? energy[gs - 1] : 0.f;
        ((float*)(smem + SM_E2))[tid] = (s < SS - 1) ? energy[gs + 1] : 0.f;
    }

    float4 pre[4];  // prefetched A fp32 (2 tasks x 8 floats)

    // A gmem->regs (value fp32), tasks: 512 = 64 rows x 8 chunks of 8 floats
    auto ldA = [&](int ch) {
        int kb = ch * 64;
#pragma unroll
        for (int q = 0; q < 2; ++q) {
            int t = tid * 2 + q, r = t >> 3, c = t & 7;
            const float4* src =
                (const float4*)(value + (grow0 + r) * DD + kb + c * 8);
            pre[q * 2]     = src[0];
            pre[q * 2 + 1] = src[1];
        }
    };
    // regs -> SMEM fp16 (swizzled)
    auto stsA = [&](int ch) {
        char* ah = smem + ((ch & 1) ? SM_AH1 : SM_AH0);
#pragma unroll
        for (int q = 0; q < 2; ++q) {
            int t = tid * 2 + q, r = t >> 3, c = t & 7;
            uint32_t off = swz((uint32_t)r, (uint32_t)c * 16);
            uint32_t hh[4];
#pragma unroll
            for (int j = 0; j < 2; ++j) {
                float4 v = pre[q * 2 + j];
                hh[j * 2]     = packh(__float2half_rn(v.x), __float2half_rn(v.y));
                hh[j * 2 + 1] = packh(__float2half_rn(v.z), __float2half_rn(v.w));
            }
            *(uint4*)(ah + off) = make_uint4(hh[0], hh[1], hh[2], hh[3]);
        }
    };
    // B tile via cp.async: 512n x 64k fp16 = 4096 x 16B
    auto cpB = [&](int ch) {
        int kb = ch * 64;
        uint32_t bbuf = sb + ((ch & 1) ? SM_B1 : SM_B0);
#pragma unroll
        for (int q = 0; q < 16; ++q) {
            int t = tid + q * 256, n = t >> 3, c = t & 7;
            cp16(bbuf + swz((uint32_t)n, (uint32_t)c * 16),
                 g_wvt + n * DD + kb + c * 8);
        }
        cp_commit();
    };

    float acc[4][8][4];
#pragma unroll
    for (int i = 0; i < 4; ++i)
#pragma unroll
        for (int j = 0; j < 8; ++j)
#pragma unroll
            for (int c = 0; c < 4; ++c) acc[i][j][c] = 0.f;

    const int nwb = wid * 64;

    auto compute = [&](int ch) {
        uint32_t abh = sb + ((ch & 1) ? SM_AH1 : SM_AH0);
        uint32_t bb  = sb + ((ch & 1) ? SM_B1 : SM_B0);
#pragma unroll
        for (int s = 0; s < 4; ++s) {
            uint32_t bfr[8][2];
#pragma unroll
            for (int np = 0; np < 4; ++np) {
                uint32_t row = nwb + np * 16 + ((lid & 16) >> 1) + (lid & 7);
                uint32_t col = s * 32 + ((lid & 8) << 1);
                ldsm4(bfr[np * 2][0], bfr[np * 2][1],
                      bfr[np * 2 + 1][0], bfr[np * 2 + 1][1],
                      bb + swz(row, col));
            }
#pragma unroll
            for (int mi = 0; mi < 4; ++mi) {
                uint32_t row = mi * 16 + (lid & 15);
                uint32_t col = s * 32 + (lid & 16);
                uint32_t ah[4];
                ldsm4(ah[0], ah[1], ah[2], ah[3], abh + swz(row, col));
#pragma unroll
                for (int ni = 0; ni < 8; ++ni)
                    mma16816(acc[mi][ni], ah, bfr[ni]);
            }
        }
    };

    // ---- pipelined K loop (8 chunks of 64) ----
    ldA(0);
    cpB(0);
    stsA(0);
    for (int ch = 0; ch < 8; ++ch) {
        cp_wait0();           // B(ch) arrived (only outstanding group)
        __syncthreads();      // A(ch) STS + B(ch) visible; prev compute done
        if (ch < 7) { ldA(ch + 1); cpB(ch + 1); }
        compute(ch);
        if (ch < 7) stsA(ch + 1);
    }

    // ---- epilogue: x = acc + qw + conv(e); score += tanh(x)*sw ----
    const float* E0 = (const float*)(smem + SM_E0);
    const float* E1 = (const float*)(smem + SM_E1);
    const float* E2 = (const float*)(smem + SM_E2);
    float e0r[8], e1r[8], e2r[8];
#pragma unroll
    for (int mi = 0; mi < 4; ++mi)
#pragma unroll
        for (int h = 0; h < 2; ++h) {
            int r = mi * 16 + h * 8 + (lid >> 2);
            e0r[mi * 2 + h] = E0[r];
            e1r[mi * 2 + h] = E1[r];
            e2r[mi * 2 + h] = E2[r];
        }
    float part[8];
#pragma unroll
    for (int i = 0; i < 8; ++i) part[i] = 0.f;

#pragma unroll
    for (int ni = 0; ni < 8; ++ni) {
        int d0 = nwb + ni * 8 + 2 * (lid & 3);
        float qb0 = c_qwb[d0], qb1 = c_qwb[d0 + 1];
        float w00 = c_cw0[d0], w01 = c_cw0[d0 + 1];
        float w10 = c_cw1[d0], w11 = c_cw1[d0 + 1];
        float w20 = c_cw2[d0], w21 = c_cw2[d0 + 1];
        float sw0 = c_sw[d0],  sw1 = c_sw[d0 + 1];
#pragma unroll
        for (int mi = 0; mi < 4; ++mi)
#pragma unroll
            for (int h = 0; h < 2; ++h) {
                int pi = mi * 2 + h;
                float x0 = acc[mi][ni][h * 2] + qb0
                         + e0r[pi] * w00 + e1r[pi] * w10 + e2r[pi] * w20;
                float x1 = acc[mi][ni][h * 2 + 1] + qb1
                         + e0r[pi] * w01 + e1r[pi] * w11 + e2r[pi] * w21;
                float t0 = 1.f - __fdividef(2.f, __expf(2.f * x0) + 1.f);
                float t1 = 1.f - __fdividef(2.f, __expf(2.f * x1) + 1.f);
                part[pi] = fmaf(t0, sw0, fmaf(t1, sw1, part[pi]));
            }
    }
#pragma unroll
    for (int pi = 0; pi < 8; ++pi) {
        part[pi] += __shfl_xor_sync(0xffffffffu, part[pi], 1);
        part[pi] += __shfl_xor_sync(0xffffffffu, part[pi], 2);
    }
    float* red = (float*)(smem + SM_RED);
    if ((lid & 3) == 0) {
#pragma unroll
        for (int mi = 0; mi < 4; ++mi)
#pragma unroll
            for (int h = 0; h < 2; ++h) {
                int r = mi * 16 + h * 8 + (lid >> 2);
                red[r * 8 + wid] = part[mi * 2 + h];
            }
    }
    __syncthreads();
    if (tid < 64) {
        float sum = score_b[0];
#pragma unroll
        for (int w = 0; w < 8; ++w) sum += red[tid * 8 + w];
        g_scores[b * SS + s0 + tid] = sum;
    }
}

// ============================================================================
// softmax per batch -> align  (256 threads, shuffle reduce)
// ============================================================================
__global__ void softmax_kernel(float* __restrict__ align_out) {
    __shared__ float wred[8];
    int b = blockIdx.x, t = threadIdx.x, w = t >> 5, l = t & 31;
    const float4* s4 = (const float4*)(g_scores + b * SS);
    float4 v0 = s4[t];
    float4 v1 = s4[t + 256];
    float m = fmaxf(fmaxf(fmaxf(v0.x, v0.y), fmaxf(v0.z, v0.w)),
                    fmaxf(fmaxf(v1.x, v1.y), fmaxf(v1.z, v1.w)));
#pragma unroll
    for (int o = 16; o > 0; o >>= 1)
        m = fmaxf(m, __shfl_xor_sync(0xffffffffu, m, o));
    if (l == 0) wred[w] = m;
    __syncthreads();
    m = wred[0];
#pragma unroll
    for (int i = 1; i < 8; ++i) m = fmaxf(m, wred[i]);
    __syncthreads();

    float4 e0, e1;
    e0.x = __expf(v0.x - m); e0.y = __expf(v0.y - m);
    e0.z = __expf(v0.z - m); e0.w = __expf(v0.w - m);
    e1.x = __expf(v1.x - m); e1.y = __expf(v1.y - m);
    e1.z = __expf(v1.z - m); e1.w = __expf(v1.w - m);
    float sum = e0.x + e0.y + e0.z + e0.w + e1.x + e1.y + e1.z + e1.w;
#pragma unroll
    for (int o = 16; o > 0; o >>= 1)
        sum += __shfl_xor_sync(0xffffffffu, sum, o);
    if (l == 0) wred[w] = sum;
    __syncthreads();
    sum = wred[0];
#pragma unroll
    for (int i = 1; i < 8; ++i) sum += wred[i];
    float inv = 1.f / sum;
    e0.x *= inv; e0.y *= inv; e0.z *= inv; e0.w *= inv;
    e1.x *= inv; e1.y *= inv; e1.z *= inv; e1.w *= inv;
    float4* a4 = (float4*)(align_out + b * SS);
    a4[t] = e0;
    a4[t + 256] = e1;
}

// ============================================================================
// context: ctx[b,d] = sum_s align[b,s] * value[b,s,d]
// ============================================================================
__global__ void zero_ctx_kernel(float* __restrict__ ctx) {
    int i = blockIdx.x * blockDim.x + threadIdx.x;
    if (i < BB * DD) ctx[i] = 0.f;
}
__global__ void context_kernel(const float* __restrict__ value,
                               const float* __restrict__ align,
                               float* __restrict__ ctx) {
    int b = blockIdx.x, dch = blockIdx.y, sch = blockIdx.z;
    int d = dch * 128 + threadIdx.x;
    const float* vb = value + ((size_t)b * SS + sch * 256) * DD + d;
    const float* ab = align + b * SS + sch * 256;
    float acc = 0.f;
#pragma unroll 8
    for (int s = 0; s < 256; ++s)
        acc = fmaf(ab[s], vb[(size_t)s * DD], acc);
    atomicAdd(&ctx[b * DD + d], acc);
}

// ============================================================================
// launch
// ============================================================================
extern "C" void kernel_launch(void* const* d_in, const int* in_sizes, int n_in,
                              void* d_out, int out_size) {
    const float* query   = (const float*)d_in[0];
    const float* value   = (const float*)d_in[1];
    const float* energy  = (const float*)d_in[2];
    const float* conv_w  = (const float*)d_in[3];
    const float* conv_b  = (const float*)d_in[4];
    const float* w_q     = (const float*)d_in[5];
    const float* w_v     = (const float*)d_in[6];
    const float* bias    = (const float*)d_in[7];
    const float* score_w = (const float*)d_in[8];
    const float* score_b = (const float*)d_in[9];
    float* out_ctx   = (float*)d_out;            // [B*D]
    float* out_align = (float*)d_out + BB * DD;  // [B*S]

    cudaFuncSetAttribute(scores_kernel,
                         cudaFuncAttributeMaxDynamicSharedMemorySize, SM_TOT);

    prep_wv_kernel<<<DD, 256>>>(w_v);
    prep_qw_kernel<<<BB, DD>>>(query, w_q, bias, conv_b);
    scores_kernel<<<BB * (SS / 64), 256, SM_TOT>>>(value, energy, conv_w,
                                                   score_w, score_b);
    softmax_kernel<<<BB, 256>>>(out_align);
    zero_ctx_kernel<<<(BB * DD + 255) / 256, 256>>>(out_ctx);
    context_kernel<<<dim3(BB, DD / 128, SS / 256), 128>>>(value, out_align,
                                                          out_ctx);
}

// round 4
// speedup vs baseline: 1.4116x; 1.1023x over previous
#include <cuda_runtime.h>
#include <cuda_fp16.h>
#include <cstdint>

// ============================================================================
// LocationAwareAttention  B=32, S=2048, D=512   (family-common PTX only:
// mma.sync.m16n8k16.f16 + ldmatrix + cp.async — NO tcgen05, target is sm_103)
//
// R4: 3-stage cp.async pipeline for the B tile (lookahead 2 chunks).
// R3 analysis: legacy HMMA rt ~8cyc/SMSP -> compute floor ~63us, but the
// 1-deep B lookahead left only ~500cyc slack per chunk -> L2 contention
// stalls. 3 stages give ~4100cyc slack.
// Output: d_out = [ctx (B*D) | align (B*S)] fp32
// ============================================================================

#define BB 32
#define SS 2048
#define DD 512

__device__ __half g_wvt[DD * DD];     // w_v^T [n][k] fp16
__device__ float  g_qw[BB * DD];      // q@w_q + bias + conv_b
__device__ float  g_scores[BB * SS];

// ---------------- SMEM layout (bytes) ----------------
#define SM_B0   0                      // B tile: 3 stages x (512n x 64k fp16=64KB)
#define SM_BSZ  65536
#define SM_A0   196608                 // A: 2 stages x (64 x 64 fp16 = 8KB)
#define SM_A1   204800
#define SM_QWB  212992                 // 512 f32
#define SM_CW0  (SM_QWB + 2048)
#define SM_CW1  (SM_CW0 + 2048)
#define SM_CW2  (SM_CW1 + 2048)
#define SM_SW   (SM_CW2 + 2048)
#define SM_E0   (SM_SW + 2048)         // 64 f32
#define SM_E1   (SM_E0 + 256)
#define SM_E2   (SM_E1 + 256)
#define SM_RED  (SM_E2 + 256)          // 64 x 8 f32
#define SM_TOT  (SM_RED + 2048)        // 226048 B

// ---------------- PTX helpers (sm_80-baseline instructions) ----------------
__device__ __forceinline__ uint32_t s2u(const void* p) {
    uint32_t a;
    asm("{ .reg .u64 t; cvta.to.shared.u64 t, %1; cvt.u32.u64 %0, t; }"
        : "=r"(a) : "l"(p));
    return a;
}
__device__ __forceinline__ void cp16(uint32_t dst, const void* src) {
    asm volatile("cp.async.ca.shared.global [%0], [%1], 16;"
                 :: "r"(dst), "l"(src) : "memory");
}
__device__ __forceinline__ void cp_commit() {
    asm volatile("cp.async.commit_group;" ::: "memory");
}
__device__ __forceinline__ void cp_wait0() {
    asm volatile("cp.async.wait_group 0;" ::: "memory");
}
__device__ __forceinline__ void cp_wait1() {
    asm volatile("cp.async.wait_group 1;" ::: "memory");
}
__device__ __forceinline__ void ldsm4(uint32_t& r0, uint32_t& r1,
                                      uint32_t& r2, uint32_t& r3, uint32_t a) {
    asm volatile("ldmatrix.sync.aligned.m8n8.x4.shared.b16 {%0,%1,%2,%3}, [%4];"
                 : "=r"(r0), "=r"(r1), "=r"(r2), "=r"(r3) : "r"(a));
}
__device__ __forceinline__ void mma16816(float* d, const uint32_t* a,
                                         const uint32_t* b) {
    asm volatile(
        "mma.sync.aligned.m16n8k16.row.col.f32.f16.f16.f32 "
        "{%0,%1,%2,%3}, {%4,%5,%6,%7}, {%8,%9}, {%0,%1,%2,%3};"
        : "+f"(d[0]), "+f"(d[1]), "+f"(d[2]), "+f"(d[3])
        : "r"(a[0]), "r"(a[1]), "r"(a[2]), "r"(a[3]), "r"(b[0]), "r"(b[1]));
}
__device__ __forceinline__ uint32_t packh(__half a, __half b) {
    __half2 h2; h2.x = a; h2.y = b;
    return *(uint32_t*)&h2;
}
// swizzled in-tile byte offset: rows of 128B, 16B-chunk rotation by (row&7)
__device__ __forceinline__ uint32_t swz(uint32_t row, uint32_t colByte) {
    return row * 128u + (colByte ^ ((row & 7u) << 4));
}

// ============================================================================
// prep: w_v^T -> fp16  [n][k]
// ============================================================================
__global__ void prep_wv_kernel(const float* __restrict__ w_v) {
    int n = blockIdx.x;
    for (int k = threadIdx.x; k < DD; k += blockDim.x)
        g_wvt[n * DD + k] = __float2half_rn(w_v[k * DD + n]);
}

// ============================================================================
// prep: g_qw[b,d] = q[b]@w_q[:,d] + bias[d] + conv_b[d]
// 8 independent accumulator chains (was latency-bound).
// ============================================================================
__global__ void prep_qw_kernel(const float* __restrict__ query,
                               const float* __restrict__ w_q,
                               const float* __restrict__ bias,
                               const float* __restrict__ conv_b) {
    __shared__ float qs[DD];
    int b = blockIdx.x, d = threadIdx.x;
    qs[d] = query[b * DD + d];
    __syncthreads();
    float a0 = 0.f, a1 = 0.f, a2 = 0.f, a3 = 0.f;
    float a4 = 0.f, a5 = 0.f, a6 = 0.f, a7 = 0.f;
#pragma unroll 8
    for (int k = 0; k < DD; k += 8) {
        a0 = fmaf(qs[k],     w_q[(k)     * DD + d], a0);
        a1 = fmaf(qs[k + 1], w_q[(k + 1) * DD + d], a1);
        a2 = fmaf(qs[k + 2], w_q[(k + 2) * DD + d], a2);
        a3 = fmaf(qs[k + 3], w_q[(k + 3) * DD + d], a3);
        a4 = fmaf(qs[k + 4], w_q[(k + 4) * DD + d], a4);
        a5 = fmaf(qs[k + 5], w_q[(k + 5) * DD + d], a5);
        a6 = fmaf(qs[k + 6], w_q[(k + 6) * DD + d], a6);
        a7 = fmaf(qs[k + 7], w_q[(k + 7) * DD + d], a7);
    }
    g_qw[b * DD + d] = bias[d] + conv_b[d]
                     + ((a0 + a1) + (a2 + a3)) + ((a4 + a5) + (a6 + a7));
}

// ============================================================================
// scores: per block M=64 rows x N=512 (full D), K=512, single fp16 pass.
// Grid: 1024 blocks (b*32 + tile), 256 threads (8 warps, warp tile 64x64).
// ============================================================================
__global__ void __launch_bounds__(256, 1)
scores_kernel(const float* __restrict__ value,
              const float* __restrict__ energy,
              const float* __restrict__ conv_w,
              const float* __restrict__ score_w,
              const float* __restrict__ score_b) {
    extern __shared__ char smem[];
    const uint32_t sb = s2u(smem);
    const int tid = threadIdx.x, wid = tid >> 5, lid = tid & 31;
    const int b = blockIdx.x >> 5, tile = blockIdx.x & 31;
    const int s0 = tile * 64;
    const size_t grow0 = (size_t)b * SS + s0;

    // ---- epilogue constants ----
    float* c_qwb = (float*)(smem + SM_QWB);
    float* c_cw0 = (float*)(smem + SM_CW0);
    float* c_cw1 = (float*)(smem + SM_CW1);
    float* c_cw2 = (float*)(smem + SM_CW2);
    float* c_sw  = (float*)(smem + SM_SW);
    for (int d = tid; d < DD; d += 256) {
        c_qwb[d] = g_qw[b * DD + d];
        c_cw0[d] = conv_w[d * 3 + 0];
        c_cw1[d] = conv_w[d * 3 + 1];
        c_cw2[d] = conv_w[d * 3 + 2];
        c_sw[d]  = score_w[d];
    }
    if (tid < 64) {
        int s = s0 + tid, gs = b * SS + s;
        ((float*)(smem + SM_E1))[tid] = energy[gs];
        ((float*)(smem + SM_E0))[tid] = (s > 0)      ? energy[gs - 1] : 0.f;
        ((float*)(smem + SM_E2))[tid] = (s < SS - 1) ? energy[gs + 1] : 0.f;
    }

    float4 pre[4];  // prefetched A fp32 (2 tasks x 8 floats)

    // A gmem->regs (value fp32), tasks: 512 = 64 rows x 8 chunks of 8 floats
    auto ldA = [&](int ch) {
        int kb = ch * 64;
#pragma unroll
        for (int q = 0; q < 2; ++q) {
            int t = tid * 2 + q, r = t >> 3, c = t & 7;
            const float4* src =
                (const float4*)(value + (grow0 + r) * DD + kb + c * 8);
            pre[q * 2]     = src[0];
            pre[q * 2 + 1] = src[1];
        }
    };
    // regs -> SMEM fp16 (swizzled), A double buffer by parity
    auto stsA = [&](int ch) {
        char* ah = smem + ((ch & 1) ? SM_A1 : SM_A0);
#pragma unroll
        for (int q = 0; q < 2; ++q) {
            int t = tid * 2 + q, r = t >> 3, c = t & 7;
            uint32_t off = swz((uint32_t)r, (uint32_t)c * 16);
            uint32_t hh[4];
#pragma unroll
            for (int j = 0; j < 2; ++j) {
                float4 v = pre[q * 2 + j];
                hh[j * 2]     = packh(__float2half_rn(v.x), __float2half_rn(v.y));
                hh[j * 2 + 1] = packh(__float2half_rn(v.z), __float2half_rn(v.w));
            }
            *(uint4*)(ah + off) = make_uint4(hh[0], hh[1], hh[2], hh[3]);
        }
    };
    // B tile via cp.async: 512n x 64k fp16 = 4096 x 16B, 3-stage ring
    auto cpB = [&](int ch) {
        int kb = ch * 64;
        uint32_t bbuf = sb + SM_B0 + (uint32_t)(ch % 3) * SM_BSZ;
#pragma unroll
        for (int q = 0; q < 16; ++q) {
            int t = tid + q * 256, n = t >> 3, c = t & 7;
            cp16(bbuf + swz((uint32_t)n, (uint32_t)c * 16),
                 g_wvt + n * DD + kb + c * 8);
        }
        cp_commit();
    };

    float acc[4][8][4];
#pragma unroll
    for (int i = 0; i < 4; ++i)
#pragma unroll
        for (int j = 0; j < 8; ++j)
#pragma unroll
            for (int c = 0; c < 4; ++c) acc[i][j][c] = 0.f;

    const int nwb = wid * 64;

    auto compute = [&](int ch) {
        uint32_t abh = sb + ((ch & 1) ? SM_A1 : SM_A0);
        uint32_t bb  = sb + SM_B0 + (uint32_t)(ch % 3) * SM_BSZ;
#pragma unroll
        for (int s = 0; s < 4; ++s) {
            uint32_t bfr[8][2];
#pragma unroll
            for (int np = 0; np < 4; ++np) {
                uint32_t row = nwb + np * 16 + ((lid & 16) >> 1) + (lid & 7);
                uint32_t col = s * 32 + ((lid & 8) << 1);
                ldsm4(bfr[np * 2][0], bfr[np * 2][1],
                      bfr[np * 2 + 1][0], bfr[np * 2 + 1][1],
                      bb + swz(row, col));
            }
#pragma unroll
            for (int mi = 0; mi < 4; ++mi) {
                uint32_t row = mi * 16 + (lid & 15);
                uint32_t col = s * 32 + (lid & 16);
                uint32_t ah[4];
                ldsm4(ah[0], ah[1], ah[2], ah[3], abh + swz(row, col));
#pragma unroll
                for (int ni = 0; ni < 8; ++ni)
                    mma16816(acc[mi][ni], ah, bfr[ni]);
            }
        }
    };

    // ---- pipelined K loop (8 chunks of 64, B 2 chunks ahead) ----
    ldA(0);
    cpB(0);            // group for chunk 0
    stsA(0);
    cpB(1);            // group for chunk 1
    ldA(1);            // regs hold A(1)
    for (int ch = 0; ch < 8; ++ch) {
        if (ch < 7) cp_wait1();   // B(ch) done, B(ch+1) may be in flight
        else        cp_wait0();   // last chunk: drain
        __syncthreads();          // A(ch) visible; all warps past compute(ch-1)
        if (ch < 6) cpB(ch + 2);  // start transfer 2 ahead
        if (ch < 7) stsA(ch + 1); // consume pre regs into A[(ch+1)&1]
        if (ch < 6) ldA(ch + 2);  // refill pre regs
        compute(ch);
    }

    // ---- epilogue: x = acc + qw + conv(e); score += tanh(x)*sw ----
    const float* E0 = (const float*)(smem + SM_E0);
    const float* E1 = (const float*)(smem + SM_E1);
    const float* E2 = (const float*)(smem + SM_E2);
    float e0r[8], e1r[8], e2r[8];
#pragma unroll
    for (int mi = 0; mi < 4; ++mi)
#pragma unroll
        for (int h = 0; h < 2; ++h) {
            int r = mi * 16 + h * 8 + (lid >> 2);
            e0r[mi * 2 + h] = E0[r];
            e1r[mi * 2 + h] = E1[r];
            e2r[mi * 2 + h] = E2[r];
        }
    float part[8];
#pragma unroll
    for (int i = 0; i < 8; ++i) part[i] = 0.f;

#pragma unroll
    for (int ni = 0; ni < 8; ++ni) {
        int d0 = nwb + ni * 8 + 2 * (lid & 3);
        float qb0 = c_qwb[d0], qb1 = c_qwb[d0 + 1];
        float w00 = c_cw0[d0], w01 = c_cw0[d0 + 1];
        float w10 = c_cw1[d0], w11 = c_cw1[d0 + 1];
        float w20 = c_cw2[d0], w21 = c_cw2[d0 + 1];
        float sw0 = c_sw[d0],  sw1 = c_sw[d0 + 1];
#pragma unroll
        for (int mi = 0; mi < 4; ++mi)
#pragma unroll
            for (int h = 0; h < 2; ++h) {
                int pi = mi * 2 + h;
                float x0 = acc[mi][ni][h * 2] + qb0
                         + e0r[pi] * w00 + e1r[pi] * w10 + e2r[pi] * w20;
                float x1 = acc[mi][ni][h * 2 + 1] + qb1
                         + e0r[pi] * w01 + e1r[pi] * w11 + e2r[pi] * w21;
                float t0 = 1.f - __fdividef(2.f, __expf(2.f * x0) + 1.f);
                float t1 = 1.f - __fdividef(2.f, __expf(2.f * x1) + 1.f);
                part[pi] = fmaf(t0, sw0, fmaf(t1, sw1, part[pi]));
            }
    }
#pragma unroll
    for (int pi = 0; pi < 8; ++pi) {
        part[pi] += __shfl_xor_sync(0xffffffffu, part[pi], 1);
        part[pi] += __shfl_xor_sync(0xffffffffu, part[pi], 2);
    }
    float* red = (float*)(smem + SM_RED);
    if ((lid & 3) == 0) {
#pragma unroll
        for (int mi = 0; mi < 4; ++mi)
#pragma unroll
            for (int h = 0; h < 2; ++h) {
                int r = mi * 16 + h * 8 + (lid >> 2);
                red[r * 8 + wid] = part[mi * 2 + h];
            }
    }
    __syncthreads();
    if (tid < 64) {
        float sum = score_b[0];
#pragma unroll
        for (int w = 0; w < 8; ++w) sum += red[tid * 8 + w];
        g_scores[b * SS + s0 + tid] = sum;
    }
}

// ============================================================================
// softmax per batch -> align  (256 threads, shuffle reduce)
// ============================================================================
__global__ void softmax_kernel(float* __restrict__ align_out) {
    __shared__ float wred[8];
    int b = blockIdx.x, t = threadIdx.x, w = t >> 5, l = t & 31;
    const float4* s4 = (const float4*)(g_scores + b * SS);
    float4 v0 = s4[t];
    float4 v1 = s4[t + 256];
    float m = fmaxf(fmaxf(fmaxf(v0.x, v0.y), fmaxf(v0.z, v0.w)),
                    fmaxf(fmaxf(v1.x, v1.y), fmaxf(v1.z, v1.w)));
#pragma unroll
    for (int o = 16; o > 0; o >>= 1)
        m = fmaxf(m, __shfl_xor_sync(0xffffffffu, m, o));
    if (l == 0) wred[w] = m;
    __syncthreads();
    m = wred[0];
#pragma unroll
    for (int i = 1; i < 8; ++i) m = fmaxf(m, wred[i]);
    __syncthreads();

    float4 e0, e1;
    e0.x = __expf(v0.x - m); e0.y = __expf(v0.y - m);
    e0.z = __expf(v0.z - m); e0.w = __expf(v0.w - m);
    e1.x = __expf(v1.x - m); e1.y = __expf(v1.y - m);
    e1.z = __expf(v1.z - m); e1.w = __expf(v1.w - m);
    float sum = e0.x + e0.y + e0.z + e0.w + e1.x + e1.y + e1.z + e1.w;
#pragma unroll
    for (int o = 16; o > 0; o >>= 1)
        sum += __shfl_xor_sync(0xffffffffu, sum, o);
    if (l == 0) wred[w] = sum;
    __syncthreads();
    sum = wred[0];
#pragma unroll
    for (int i = 1; i < 8; ++i) sum += wred[i];
    float inv = 1.f / sum;
    e0.x *= inv; e0.y *= inv; e0.z *= inv; e0.w *= inv;
    e1.x *= inv; e1.y *= inv; e1.z *= inv; e1.w *= inv;
    float4* a4 = (float4*)(align_out + b * SS);
    a4[t] = e0;
    a4[t + 256] = e1;
}

// ============================================================================
// context: ctx[b,d] = sum_s align[b,s] * value[b,s,d]
// ============================================================================
__global__ void zero_ctx_kernel(float* __restrict__ ctx) {
    int i = blockIdx.x * blockDim.x + threadIdx.x;
    if (i < BB * DD) ctx[i] = 0.f;
}
__global__ void context_kernel(const float* __restrict__ value,
                               const float* __restrict__ align,
                               float* __restrict__ ctx) {
    int b = blockIdx.x, dch = blockIdx.y, sch = blockIdx.z;
    int d = dch * 128 + threadIdx.x;
    const float* vb = value + ((size_t)b * SS + sch * 256) * DD + d;
    const float* ab = align + b * SS + sch * 256;
    float acc = 0.f;
#pragma unroll 8
    for (int s = 0; s < 256; ++s)
        acc = fmaf(ab[s], vb[(size_t)s * DD], acc);
    atomicAdd(&ctx[b * DD + d], acc);
}

// ============================================================================
// launch
// ============================================================================
extern "C" void kernel_launch(void* const* d_in, const int* in_sizes, int n_in,
                              void* d_out, int out_size) {
    const float* query   = (const float*)d_in[0];
    const float* value   = (const float*)d_in[1];
    const float* energy  = (const float*)d_in[2];
    const float* conv_w  = (const float*)d_in[3];
    const float* conv_b  = (const float*)d_in[4];
    const float* w_q     = (const float*)d_in[5];
    const float* w_v     = (const float*)d_in[6];
    const float* bias    = (const float*)d_in[7];
    const float* score_w = (const float*)d_in[8];
    const float* score_b = (const float*)d_in[9];
    float* out_ctx   = (float*)d_out;            // [B*D]
    float* out_align = (float*)d_out + BB * DD;  // [B*S]

    cudaFuncSetAttribute(scores_kernel,
                         cudaFuncAttributeMaxDynamicSharedMemorySize, SM_TOT);

    zero_ctx_kernel<<<(BB * DD + 255) / 256, 256>>>(out_ctx);
    prep_wv_kernel<<<DD, 256>>>(w_v);
    prep_qw_kernel<<<BB, DD>>>(query, w_q, bias, conv_b);
    scores_kernel<<<BB * (SS / 64), 256, SM_TOT>>>(value, energy, conv_w,
                                                   score_w, score_b);
    softmax_kernel<<<BB, 256>>>(out_align);
    context_kernel<<<dim3(BB, DD / 128, SS / 256), 128>>>(value, out_align,
                                                          out_ctx);
}